// round 3
// baseline (speedup 1.0000x reference)
#include <cuda_runtime.h>
#include <cuda_bf16.h>
#include <cstdint>

#define Bn 128
#define Tn 256
#define NHID 1024
#define NIN 128
#define NOUT 64
#define NCTA 128
#define THREADS 512

// output layout: hidden_list [128][256][1024] ++ output_list [128][256][64] ++ h_final [128][1024]
#define OUT_HID 0
#define OUT_OUT 33554432
#define OUT_HF  35651584

// -------- device scratch (no allocations allowed) --------
__device__ float g_act[2][NHID * Bn];            // tanh(h), [k][b], double buffered
__device__ float g_xT[Tn * NIN * Bn];            // x transposed per t: [t][i][b]
__device__ float g_outpart[2][32 * Bn * NOUT];   // out partials [jg][b][o]
__device__ unsigned g_arrive;
__device__ unsigned g_release;

typedef unsigned long long ull;

__device__ __forceinline__ ull pack2(float x) {
    ull r; asm("mov.b64 %0, {%1, %1};" : "=l"(r) : "f"(x)); return r;
}
__device__ __forceinline__ void fma2(ull& c, ull a, ull b) {
    asm("fma.rn.f32x2 %0, %1, %2, %0;" : "+l"(c) : "l"(a), "l"(b));
}
__device__ __forceinline__ float2 unpack2(ull v) {
    float2 f; asm("mov.b64 {%0, %1}, %2;" : "=f"(f.x), "=f"(f.y) : "l"(v)); return f;
}
__device__ __forceinline__ void cpasync16(uint32_t dst, const float* src) {
    asm volatile("cp.async.cg.shared.global [%0], [%1], 16;" :: "r"(dst), "l"(src));
}
__device__ __forceinline__ void cpcommit() { asm volatile("cp.async.commit_group;"); }
template<int N> __device__ __forceinline__ void cpwait() {
    asm volatile("cp.async.wait_group %0;" :: "n"(N));
}

// -------- x transpose: g_xT[t][i][b] = input_signal[b][t][i] --------
__global__ void xT_kernel(const float* __restrict__ in) {
    __shared__ float s[128][33];
    int t = blockIdx.x >> 2, ig = blockIdx.x & 3;
    for (int idx = threadIdx.x; idx < 128 * 32; idx += 256) {
        int b = idx >> 5, ii = idx & 31;
        s[b][ii] = in[b * (Tn * NIN) + t * NIN + ig * 32 + ii];
    }
    __syncthreads();
    for (int idx = threadIdx.x; idx < 4096; idx += 256) {
        int ii = idx >> 7, b = idx & 127;
        g_xT[t * (NIN * Bn) + (ig * 32 + ii) * Bn + b] = s[b][ii];
    }
}

// -------- smem layout (floats) --------
#define SM_W    0                      // w slices [1152][32]
#define SM_ACT  (SM_W + 1152 * 32)     // act double buffer [2][128][32]
#define SM_WO   (SM_ACT + 2 * 4096)    // w_out slice [32][64]
#define SM_HJ   (SM_WO + 2048)         // h staged [j][b]  [32][36]
#define SM_HB   (SM_HJ + 32 * 36)      // h staged [b][j]  [32][36]
#define SM_TJ   (SM_HB + 32 * 36)      // tanh(h) [j][b]   [32][36]
#define SM_RED  (SM_TJ + 32 * 36)      // k-split partials [4][128][8]
#define SM_FLOATS (SM_RED + 4 * 128 * 8)
#define SMEM_BYTES (SM_FLOATS * 4)

__global__ void __launch_bounds__(THREADS, 1)
rnn_main(const float* __restrict__ hidden,
         const float* __restrict__ w_in,
         const float* __restrict__ w_hh,
         const float* __restrict__ w_b,
         const float* __restrict__ w_out,
         const float* __restrict__ alpha,
         const float* __restrict__ noise,
         const int* __restrict__ ptp,
         float* __restrict__ out)
{
    extern __shared__ float sm[];
    float* w_s   = sm + SM_W;
    float* act_s = sm + SM_ACT;
    float* wo_s  = sm + SM_WO;
    float* hj    = sm + SM_HJ;
    float* hb    = sm + SM_HB;
    float* tj    = sm + SM_TJ;
    float* red   = sm + SM_RED;

    const int tid = threadIdx.x;
    const int cta = blockIdx.x;
    const int jg = cta & 31, bg = cta >> 5;
    const int jbase = jg * 32, bbase = bg * 32;

    const int kq   = tid >> 7;      // k-split group 0..3
    const int wtid = tid & 127;
    const int bq = wtid & 7, jq = wtid >> 3;
    const int b0 = bq * 4, j0 = jq * 2;
    const int bloc = b0 + kq;       // this thread's owned local batch row
    const int bown = bbase + bloc;

    // ---- load weight slices into smem (once, coalesced over k) ----
    {
        int jj = tid >> 4;          // 0..31
        int kk2 = tid & 15;         // 0..15
        const float* wr = w_hh + (size_t)(jbase + jj) * NHID;
        for (int k = kk2; k < NHID; k += 16)
            w_s[k * 32 + jj] = wr[k];
        const float* wi = w_in + (size_t)(jbase + jj) * NIN;
        for (int i = kk2; i < NIN; i += 16)
            w_s[(1024 + i) * 32 + jj] = wi[i];
    }
    for (int idx = tid; idx < 32 * 64; idx += THREADS) {
        int jj = idx >> 6, o = idx & 63;
        wo_s[jj * 64 + o] = w_out[o * NHID + jbase + jj];
    }

    const float al0 = alpha[jbase + j0], al1 = alpha[jbase + j0 + 1];
    const float bi0 = w_b[jbase + j0],   bi1 = w_b[jbase + j0 + 1];
    const float ns0 = 0.05f * sqrtf(al0), ns1 = 0.05f * sqrtf(al1);
    const int pt = *ptp;

    // persistent h registers: this thread owns (bown, j0, j0+1)
    float2 hv = *(const float2*)&hidden[(size_t)bown * NHID + jbase + j0];
    float h0 = hv.x, h1 = hv.y;

    // initial act buffer 0 = tanh(hidden), layout [k][b]
    g_act[0][(jbase + j0) * Bn + bown]     = tanhf(h0);
    g_act[0][(jbase + j0 + 1) * Bn + bown] = tanhf(h1);

    // grid barrier bookkeeping (monotonic, replay-safe)
    unsigned bar_t = 0;
    if (tid == 0) bar_t = *((volatile unsigned*)&g_release);

#define GRIDBAR() do {                                                        \
        __syncthreads();                                                      \
        if (tid == 0) {                                                       \
            __threadfence();                                                  \
            bar_t += (unsigned)NCTA;                                          \
            unsigned a_ = atomicAdd(&g_arrive, 1u) + 1u;                      \
            if (a_ == bar_t) { atomicExch(&g_release, bar_t); }               \
            else { while ((int)(*((volatile unsigned*)&g_release) - bar_t) < 0) {} } \
            __threadfence();                                                  \
        }                                                                     \
        __syncthreads();                                                      \
    } while (0)

    GRIDBAR();  // g_act[0] visible everywhere

    const uint32_t act_u = (uint32_t)__cvta_generic_to_shared(act_s);

    for (int t = 0; t < Tn; t++) {
        // ---- deterministic reduce of previous step's out partials ----
        if (t > 0 && tid < 64) {
            int e = cta * 64 + tid;
            const float* src = g_outpart[(t - 1) & 1];
            float s = 0.f;
            #pragma unroll
            for (int r = 0; r < 32; r++) s += src[r * 8192 + e];
            int b = e >> 6, o = e & 63;
            out[OUT_OUT + b * (Tn * NOUT) + (t - 1) * NOUT + o] = s;
        }

        const float* asrc = g_act[t & 1];
        const float* xsrc = g_xT + t * (NIN * Bn);

        ull acc00 = 0, acc01 = 0, acc10 = 0, acc11 = 0;

        // prologue: stage chunk 0 (2 cp.async per thread)
        {
            #pragma unroll
            for (int s = 0; s < 2; s++) {
                int ii = tid + s * 512;
                int r = ii >> 3, cg = ii & 7;
                cpasync16(act_u + (uint32_t)((r * 32 + cg * 4) * 4),
                          asrc + r * Bn + bbase + cg * 4);
            }
            cpcommit();
        }

        #pragma unroll 1
        for (int c = 0; c < 9; c++) {
            if (c < 8) {
                const float* src = (c + 1 < 8) ? (asrc + (c + 1) * 128 * Bn) : xsrc;
                uint32_t dst = act_u + (uint32_t)(((c + 1) & 1) * 4096 * 4);
                #pragma unroll
                for (int s = 0; s < 2; s++) {
                    int ii = tid + s * 512;
                    int r = ii >> 3, cg = ii & 7;
                    cpasync16(dst + (uint32_t)((r * 32 + cg * 4) * 4),
                              src + r * Bn + bbase + cg * 4);
                }
                cpcommit();
                cpwait<1>();
            } else {
                cpwait<0>();
            }
            __syncthreads();

            // each k-group handles 32 of the 128 kk rows of this chunk
            const float* ab = act_s + (c & 1) * 4096 + kq * 32 * 32 + b0;
            const float* wb = w_s + (c * 128 + kq * 32) * 32 + j0;
            #pragma unroll
            for (int kk = 0; kk < 32; kk++) {
                ulonglong2 aa = *(const ulonglong2*)(ab + kk * 32);
                float2 wv = *(const float2*)(wb + kk * 32);
                ull w0 = pack2(wv.x), w1 = pack2(wv.y);
                fma2(acc00, aa.x, w0); fma2(acc01, aa.x, w1);
                fma2(acc10, aa.y, w0); fma2(acc11, aa.y, w1);
            }
            __syncthreads();
        }

        // ---- cross-group reduction of k-split partials ----
        {
            float2 p00 = unpack2(acc00), p01 = unpack2(acc01);
            float2 p10 = unpack2(acc10), p11 = unpack2(acc11);
            float* rd = red + (kq * 128 + wtid) * 8;
            *(float4*)(rd)     = make_float4(p00.x, p01.x, p00.y, p01.y); // b0,b1
            *(float4*)(rd + 4) = make_float4(p10.x, p11.x, p10.y, p11.y); // b2,b3
        }
        __syncthreads();

        float t0 = bi0, t1 = bi1;
        #pragma unroll
        for (int g = 0; g < 4; g++) {
            float2 v = *(const float2*)(red + (g * 128 + wtid) * 8 + kq * 2);
            t0 += v.x; t1 += v.y;
        }

        // ---- h update (this thread's single b row, 2 j) ----
        h0 = (1.f - al0) * h0 + al0 * t0;
        h1 = (1.f - al1) * h1 + al1 * t1;
        if (t == pt) {
            const float* np = noise + (size_t)bown * NHID + jbase + j0;
            h0 += np[0] * ns0;
            h1 += np[1] * ns1;
        }

        // stage: hb [b][j] for coalesced hidden writes; hj/tj [j][b]
        *(float2*)&hb[bloc * 36 + j0] = make_float2(h0, h1);
        hj[(j0)     * 36 + bloc] = h0;
        hj[(j0 + 1) * 36 + bloc] = h1;
        tj[(j0)     * 36 + bloc] = tanhf(h0);
        tj[(j0 + 1) * 36 + bloc] = tanhf(h1);
        __syncthreads();

        // coalesced global writes (256 threads)
        if (tid < 256) {
            int rw = tid >> 3, q = tid & 7;
            float4 v = *(const float4*)(hb + rw * 36 + q * 4);
            *(float4*)&out[OUT_HID + (size_t)(bbase + rw) * (Tn * NHID) + (size_t)t * NHID + jbase + q * 4] = v;
            if (t == Tn - 1)
                *(float4*)&out[OUT_HF + (size_t)(bbase + rw) * NHID + jbase + q * 4] = v;
            float4 a = *(const float4*)(tj + rw * 36 + q * 4);  // rw = j row here
            *(float4*)&g_act[(t + 1) & 1][(jbase + rw) * Bn + bbase + q * 4] = a;
        }

        // ---- out partial GEMM: [32b x 64o], K = 32 (this CTA's j slice) ----
        {
            const int br = wtid >> 2;                 // 0..31
            const int o0 = (wtid & 3) * 4 + kq * 16;  // 0..63
            float oa0 = 0.f, oa1 = 0.f, oa2 = 0.f, oa3 = 0.f;
            #pragma unroll
            for (int j = 0; j < 32; j++) {
                float a = hj[j * 36 + br];
                float4 w4 = *(const float4*)(wo_s + j * 64 + o0);
                oa0 += a * w4.x; oa1 += a * w4.y; oa2 += a * w4.z; oa3 += a * w4.w;
            }
            float* op = g_outpart[t & 1] + jg * 8192;
            *(float4*)&op[(bbase + br) * 64 + o0] = make_float4(oa0, oa1, oa2, oa3);
        }

        GRIDBAR();
    }

    // final out reduce for t = 255
    if (tid < 64) {
        int e = cta * 64 + tid;
        const float* src = g_outpart[(Tn - 1) & 1];
        float s = 0.f;
        #pragma unroll
        for (int r = 0; r < 32; r++) s += src[r * 8192 + e];
        int b = e >> 6, o = e & 63;
        out[OUT_OUT + b * (Tn * NOUT) + (Tn - 1) * NOUT + o] = s;
    }
#undef GRIDBAR
}

// -------- launcher --------
extern "C" void kernel_launch(void* const* d_in, const int* in_sizes, int n_in,
                              void* d_out, int out_size)
{
    const float* input_signal = (const float*)d_in[0];
    const float* hidden       = (const float*)d_in[1];
    const float* w_in_w       = (const float*)d_in[2];
    const float* w_hh_w       = (const float*)d_in[3];
    const float* w_hh_b       = (const float*)d_in[4];
    const float* w_out_w      = (const float*)d_in[5];
    const float* alpha        = (const float*)d_in[6];
    const float* noise_raw    = (const float*)d_in[7];
    const int*   pt           = (const int*)d_in[8];
    float* out = (float*)d_out;

    cudaFuncSetAttribute(rnn_main, cudaFuncAttributeMaxDynamicSharedMemorySize, SMEM_BYTES);

    xT_kernel<<<1024, 256>>>(input_signal);
    rnn_main<<<NCTA, THREADS, SMEM_BYTES>>>(hidden, w_in_w, w_hh_w, w_hh_b,
                                            w_out_w, alpha, noise_raw, pt, out);
}

// round 4
// speedup vs baseline: 1.3435x; 1.3435x over previous
#include <cuda_runtime.h>
#include <cuda_bf16.h>
#include <cstdint>

#define Bn 128
#define Tn 256
#define NHID 1024
#define NIN 128
#define NOUT 64
#define KTOT 1152
#define NCTA 128
#define THREADS 256
#define JGN 64          // j-groups (16 j each)
#define JSL 16          // j per CTA

// output layout: hidden_list [128][256][1024] ++ output_list [128][256][64] ++ h_final [128][1024]
#define OUT_HID 0
#define OUT_OUT 33554432
#define OUT_HF  35651584

// -------- device scratch --------
__device__ float g_act[2][NHID * Bn];              // tanh(h) [k][b], double buffered
__device__ float g_xT[Tn * NIN * Bn];              // x transposed [t][i][b]
__device__ float g_outpart[2][JGN * Bn * NOUT];    // out partials [jg][b][o]
__device__ unsigned g_arrive;
__device__ unsigned g_release;

typedef unsigned long long ull;

__device__ __forceinline__ ull pack2(float x) {
    ull r; asm("mov.b64 %0, {%1, %1};" : "=l"(r) : "f"(x)); return r;
}
__device__ __forceinline__ void fma2(ull& c, ull a, ull b) {
    asm("fma.rn.f32x2 %0, %1, %2, %0;" : "+l"(c) : "l"(a), "l"(b));
}
__device__ __forceinline__ float2 unpack2(ull v) {
    float2 f; asm("mov.b64 {%0, %1}, %2;" : "=f"(f.x), "=f"(f.y) : "l"(v)); return f;
}
__device__ __forceinline__ void cpasync16(uint32_t dst, const float* src) {
    asm volatile("cp.async.cg.shared.global [%0], [%1], 16;" :: "r"(dst), "l"(src));
}
__device__ __forceinline__ void cpcommit() { asm volatile("cp.async.commit_group;"); }
template<int N> __device__ __forceinline__ void cpwait() {
    asm volatile("cp.async.wait_group %0;" :: "n"(N));
}

// -------- x transpose: g_xT[t][i][b] = input_signal[b][t][i] --------
__global__ void xT_kernel(const float* __restrict__ in) {
    __shared__ float s[128][33];
    int t = blockIdx.x >> 2, ig = blockIdx.x & 3;
    for (int idx = threadIdx.x; idx < 128 * 32; idx += 256) {
        int b = idx >> 5, ii = idx & 31;
        s[b][ii] = in[b * (Tn * NIN) + t * NIN + ig * 32 + ii];
    }
    __syncthreads();
    for (int idx = threadIdx.x; idx < 4096; idx += 256) {
        int ii = idx >> 7, b = idx & 127;
        g_xT[t * (NIN * Bn) + (ig * 32 + ii) * Bn + b] = s[b][ii];
    }
}

// -------- smem layout (bytes) --------
// wp (packed weights, ull): 1152*16*8 = 147456
// act double buffer:        2*128*64*4 = 65536   (red [8][64*16] = 32KB aliases act)
// wo_s:                     16*64*4 = 4096
// hj:                       16*68*4 = 4352
#define SMB_WP   0
#define SMB_ACT  147456
#define SMB_WO   (SMB_ACT + 65536)
#define SMB_HJ   (SMB_WO + 4096)
#define SMEM_BYTES (SMB_HJ + 4352)

__global__ void __launch_bounds__(THREADS, 1)
rnn_main(const float* __restrict__ hidden,
         const float* __restrict__ w_in,
         const float* __restrict__ w_hh,
         const float* __restrict__ w_b,
         const float* __restrict__ w_out,
         const float* __restrict__ alpha,
         const float* __restrict__ noise,
         const int* __restrict__ ptp,
         float* __restrict__ out)
{
    extern __shared__ char smraw[];
    ull*   wp    = (ull*)(smraw + SMB_WP);
    float* act_s = (float*)(smraw + SMB_ACT);
    float* red   = act_s;                    // alias (used after last chunk)
    float* wo_s  = (float*)(smraw + SMB_WO);
    float* hj    = (float*)(smraw + SMB_HJ);

    const int tid = threadIdx.x;
    const int cta = blockIdx.x;
    const int jg = cta & 63, bg = cta >> 6;
    const int jbase = jg * JSL, bbase = bg * 64;

    const int w   = tid >> 5;        // warp 0..7 (owns k rows: k%8 == w within chunk)
    const int lid = tid & 31;
    const int jq = lid >> 3;         // 0..3 -> 4 j (ull) at j0u
    const int bq = lid & 7;          // 0..7 -> 8 b at b0
    const int j0u = jq * 4;
    const int b0 = bq * 8;

    // ---- pre-pack weights into smem as broadcast (w,w) ulls (once) ----
    for (int idx = tid; idx < KTOT * JSL; idx += THREADS) {
        int k = idx >> 4, jj = idx & 15;
        float v = (k < NHID) ? w_hh[(size_t)(jbase + jj) * NHID + k]
                             : w_in[(size_t)(jbase + jj) * NIN + (k - NHID)];
        wp[idx] = pack2(v);
    }
    for (int idx = tid; idx < JSL * 64; idx += THREADS) {
        int jj = idx >> 6, o = idx & 63;
        wo_s[jj * 64 + o] = w_out[o * NHID + jbase + jj];
    }

    // ---- per-thread h ownership: (bloc = tid>>2, j = jr..jr+3) ----
    const int bloc = tid >> 2;
    const int jr = (tid & 3) * 4;
    const int bown = bbase + bloc;

    float4 al4 = *(const float4*)&alpha[jbase + jr];
    float4 bi4 = *(const float4*)&w_b[jbase + jr];
    float4 ns4 = make_float4(0.05f * sqrtf(al4.x), 0.05f * sqrtf(al4.y),
                             0.05f * sqrtf(al4.z), 0.05f * sqrtf(al4.w));
    const int pt = *ptp;

    float4 h = *(const float4*)&hidden[(size_t)bown * NHID + jbase + jr];

    // initial act buffer 0 = tanh(hidden)
    g_act[0][(jbase + jr + 0) * Bn + bown] = tanhf(h.x);
    g_act[0][(jbase + jr + 1) * Bn + bown] = tanhf(h.y);
    g_act[0][(jbase + jr + 2) * Bn + bown] = tanhf(h.z);
    g_act[0][(jbase + jr + 3) * Bn + bown] = tanhf(h.w);

    // grid barrier (monotonic, replay-safe)
    unsigned bar_t = 0;
    if (tid == 0) bar_t = *((volatile unsigned*)&g_release);

#define GRIDBAR() do {                                                        \
        __threadfence();                                                      \
        __syncthreads();                                                      \
        if (tid == 0) {                                                       \
            bar_t += (unsigned)NCTA;                                          \
            unsigned a_ = atomicAdd(&g_arrive, 1u) + 1u;                      \
            if (a_ == bar_t) { atomicExch(&g_release, bar_t); }               \
            else { while ((int)(*((volatile unsigned*)&g_release) - bar_t) < 0) {} } \
        }                                                                     \
        __syncthreads();                                                      \
    } while (0)

    GRIDBAR();

    const uint32_t act_u = (uint32_t)__cvta_generic_to_shared(act_s);

    for (int t = 0; t < Tn; t++) {
        // ---- deterministic reduce of previous step's out partials ----
        if (t > 0 && tid < 64) {
            int e = cta * 64 + tid;
            const float* src = g_outpart[(t - 1) & 1];
            float s = 0.f;
            #pragma unroll
            for (int r = 0; r < JGN; r++) s += __ldcg(src + r * (Bn * NOUT) + e);
            int b = e >> 6, o = e & 63;
            out[OUT_OUT + b * (Tn * NOUT) + (t - 1) * NOUT + o] = s;
        }

        const float* asrc = g_act[t & 1];
        const float* xsrc = g_xT + t * (NIN * Bn);

        ull acc[4][4];
        #pragma unroll
        for (int i = 0; i < 4; i++)
            #pragma unroll
            for (int j = 0; j < 4; j++) acc[i][j] = 0;

        // prologue: stage chunk 0 (8 cp.async16 per thread: 128 rows x 64 b)
        {
            #pragma unroll
            for (int s = 0; s < 8; s++) {
                int ii = tid + s * 256;
                int r = ii >> 4, cg = ii & 15;
                cpasync16(act_u + (uint32_t)((r * 64 + cg * 4) * 4),
                          asrc + r * Bn + bbase + cg * 4);
            }
            cpcommit();
        }

        #pragma unroll 1
        for (int c = 0; c < 9; c++) {
            if (c < 8) {
                const float* src = (c + 1 < 8) ? (asrc + (c + 1) * 128 * Bn) : xsrc;
                uint32_t dst = act_u + (uint32_t)(((c + 1) & 1) * 8192 * 4);
                #pragma unroll
                for (int s = 0; s < 8; s++) {
                    int ii = tid + s * 256;
                    int r = ii >> 4, cg = ii & 15;
                    cpasync16(dst + (uint32_t)((r * 64 + cg * 4) * 4),
                              src + r * Bn + bbase + cg * 4);
                }
                cpcommit();
                cpwait<1>();
            } else {
                cpwait<0>();
            }
            __syncthreads();

            // warp w computes rows {w, w+8, ..., w+120} of this chunk
            const float* ab = act_s + (c & 1) * 8192 + w * 64 + b0;
            const ull*   wb = wp + (c * 128 + w) * JSL + j0u;
            #pragma unroll 2
            for (int i = 0; i < 16; i++) {
                ulonglong2 a01 = *(const ulonglong2*)(ab + i * 512);
                ulonglong2 a23 = *(const ulonglong2*)(ab + i * 512 + 4);
                ulonglong2 w01 = *(const ulonglong2*)(wb + i * 128);
                ulonglong2 w23 = *(const ulonglong2*)(wb + i * 128 + 2);
                fma2(acc[0][0], a01.x, w01.x); fma2(acc[0][1], a01.x, w01.y);
                fma2(acc[0][2], a01.x, w23.x); fma2(acc[0][3], a01.x, w23.y);
                fma2(acc[1][0], a01.y, w01.x); fma2(acc[1][1], a01.y, w01.y);
                fma2(acc[1][2], a01.y, w23.x); fma2(acc[1][3], a01.y, w23.y);
                fma2(acc[2][0], a23.x, w01.x); fma2(acc[2][1], a23.x, w01.y);
                fma2(acc[2][2], a23.x, w23.x); fma2(acc[2][3], a23.x, w23.y);
                fma2(acc[3][0], a23.y, w01.x); fma2(acc[3][1], a23.y, w01.y);
                fma2(acc[3][2], a23.y, w23.x); fma2(acc[3][3], a23.y, w23.y);
            }
            __syncthreads();
        }

        // ---- dump partials to red[w] (aliases act buffer; safe after last sync) ----
        {
            float* myred = red + w * (64 * JSL);
            #pragma unroll
            for (int bp = 0; bp < 4; bp++) {
                float2 v0 = unpack2(acc[bp][0]);
                float2 v1 = unpack2(acc[bp][1]);
                float2 v2 = unpack2(acc[bp][2]);
                float2 v3 = unpack2(acc[bp][3]);
                *(float4*)(myred + (b0 + 2 * bp)     * JSL + j0u * 1 + 0) =
                    make_float4(v0.x, v1.x, v2.x, v3.x);
                *(float4*)(myred + (b0 + 2 * bp + 1) * JSL + j0u * 1 + 0) =
                    make_float4(v0.y, v1.y, v2.y, v3.y);
            }
        }
        __syncthreads();

        // ---- 8-way reduce + h update (thread owns bloc, jr..jr+3) ----
        {
            float4 s = make_float4(0.f, 0.f, 0.f, 0.f);
            #pragma unroll
            for (int g = 0; g < 8; g++) {
                float4 v = *(const float4*)(red + g * (64 * JSL) + bloc * JSL + jr);
                s.x += v.x; s.y += v.y; s.z += v.z; s.w += v.w;
            }
            s.x += bi4.x; s.y += bi4.y; s.z += bi4.z; s.w += bi4.w;
            h.x = (1.f - al4.x) * h.x + al4.x * s.x;
            h.y = (1.f - al4.y) * h.y + al4.y * s.y;
            h.z = (1.f - al4.z) * h.z + al4.z * s.z;
            h.w = (1.f - al4.w) * h.w + al4.w * s.w;
            if (t == pt) {
                float4 n = *(const float4*)&noise[(size_t)bown * NHID + jbase + jr];
                h.x += n.x * ns4.x; h.y += n.y * ns4.y;
                h.z += n.z * ns4.z; h.w += n.w * ns4.w;
            }
        }

        // hidden_list write (8 lanes per 64B row segment — coalesced enough)
        *(float4*)&out[OUT_HID + (size_t)bown * (Tn * NHID) + (size_t)t * NHID + jbase + jr] = h;
        if (t == Tn - 1)
            *(float4*)&out[OUT_HF + (size_t)bown * NHID + jbase + jr] = h;

        // next act buffer (tanh) + hj staging for out-GEMM
        {
            float t0 = tanhf(h.x), t1 = tanhf(h.y), t2 = tanhf(h.z), t3 = tanhf(h.w);
            float* ga = &g_act[(t + 1) & 1][0];
            ga[(jbase + jr + 0) * Bn + bown] = t0;
            ga[(jbase + jr + 1) * Bn + bown] = t1;
            ga[(jbase + jr + 2) * Bn + bown] = t2;
            ga[(jbase + jr + 3) * Bn + bown] = t3;
            hj[(jr + 0) * 68 + bloc] = h.x;
            hj[(jr + 1) * 68 + bloc] = h.y;
            hj[(jr + 2) * 68 + bloc] = h.z;
            hj[(jr + 3) * 68 + bloc] = h.w;
        }
        __syncthreads();

        // ---- out partial GEMM: [64b x 64o], K = 16 (this CTA's j slice) ----
        {
            const int br = tid >> 2;
            const int o0 = (tid & 3) * 16;
            float oa[16];
            #pragma unroll
            for (int i = 0; i < 16; i++) oa[i] = 0.f;
            #pragma unroll
            for (int j = 0; j < JSL; j++) {
                float a = hj[j * 68 + br];
                const float* wr = wo_s + j * 64 + o0;
                float4 w0 = *(const float4*)(wr);
                float4 w1 = *(const float4*)(wr + 4);
                float4 w2 = *(const float4*)(wr + 8);
                float4 w3 = *(const float4*)(wr + 12);
                oa[0] += a * w0.x; oa[1] += a * w0.y; oa[2]  += a * w0.z; oa[3]  += a * w0.w;
                oa[4] += a * w1.x; oa[5] += a * w1.y; oa[6]  += a * w1.z; oa[7]  += a * w1.w;
                oa[8] += a * w2.x; oa[9] += a * w2.y; oa[10] += a * w2.z; oa[11] += a * w2.w;
                oa[12]+= a * w3.x; oa[13]+= a * w3.y; oa[14] += a * w3.z; oa[15] += a * w3.w;
            }
            float* op = g_outpart[t & 1] + jg * (Bn * NOUT) + (bbase + br) * 64 + o0;
            *(float4*)(op)      = make_float4(oa[0],  oa[1],  oa[2],  oa[3]);
            *(float4*)(op + 4)  = make_float4(oa[4],  oa[5],  oa[6],  oa[7]);
            *(float4*)(op + 8)  = make_float4(oa[8],  oa[9],  oa[10], oa[11]);
            *(float4*)(op + 12) = make_float4(oa[12], oa[13], oa[14], oa[15]);
        }

        GRIDBAR();
    }

    // final out reduce for t = 255
    if (tid < 64) {
        int e = cta * 64 + tid;
        const float* src = g_outpart[(Tn - 1) & 1];
        float s = 0.f;
        #pragma unroll
        for (int r = 0; r < JGN; r++) s += __ldcg(src + r * (Bn * NOUT) + e);
        int b = e >> 6, o = e & 63;
        out[OUT_OUT + b * (Tn * NOUT) + (Tn - 1) * NOUT + o] = s;
    }
#undef GRIDBAR
}

// -------- launcher --------
extern "C" void kernel_launch(void* const* d_in, const int* in_sizes, int n_in,
                              void* d_out, int out_size)
{
    const float* input_signal = (const float*)d_in[0];
    const float* hidden       = (const float*)d_in[1];
    const float* w_in_w       = (const float*)d_in[2];
    const float* w_hh_w       = (const float*)d_in[3];
    const float* w_hh_b       = (const float*)d_in[4];
    const float* w_out_w      = (const float*)d_in[5];
    const float* alpha        = (const float*)d_in[6];
    const float* noise_raw    = (const float*)d_in[7];
    const int*   pt           = (const int*)d_in[8];
    float* out = (float*)d_out;

    cudaFuncSetAttribute(rnn_main, cudaFuncAttributeMaxDynamicSharedMemorySize, SMEM_BYTES);

    xT_kernel<<<1024, 256>>>(input_signal);
    rnn_main<<<NCTA, THREADS, SMEM_BYTES>>>(hidden, w_in_w, w_hh_w, w_hh_b,
                                            w_out_w, alpha, noise_raw, pt, out);
}

// round 5
// speedup vs baseline: 1.7354x; 1.2917x over previous
#include <cuda_runtime.h>
#include <cuda_bf16.h>
#include <cstdint>

#define Bn 128
#define Tn 256
#define NHID 1024
#define NIN 128
#define NOUT 64
#define KTOT 1152
#define NCTA 128
#define THREADS 512
#define JGN 32          // j-groups
#define JSL 32          // j per CTA

// output layout: hidden_list [128][256][1024] ++ output_list [128][256][64] ++ h_final [128][1024]
#define OUT_HID 0
#define OUT_OUT 33554432
#define OUT_HF  35651584

// -------- device scratch --------
__device__ float g_act[2][NHID * Bn];              // tanh(h) [k][b], double buffered
__device__ float g_xT[Tn * NIN * Bn];              // x transposed [t][i][b]
__device__ float g_outpart[2][JGN * Bn * NOUT];    // out partials [jg][b*64+o]
__device__ unsigned g_arrive;
__device__ unsigned g_release;

typedef unsigned long long ull;

__device__ __forceinline__ ull pack2(float x) {
    ull r; asm("mov.b64 %0, {%1, %1};" : "=l"(r) : "f"(x)); return r;
}
__device__ __forceinline__ void fma2(ull& c, ull a, ull b) {
    asm("fma.rn.f32x2 %0, %1, %2, %0;" : "+l"(c) : "l"(a), "l"(b));
}
__device__ __forceinline__ float2 unpack2(ull v) {
    float2 f; asm("mov.b64 {%0, %1}, %2;" : "=f"(f.x), "=f"(f.y) : "l"(v)); return f;
}
__device__ __forceinline__ void cpasync16(uint32_t dst, const float* src) {
    asm volatile("cp.async.cg.shared.global [%0], [%1], 16;" :: "r"(dst), "l"(src));
}
__device__ __forceinline__ void cpcommit() { asm volatile("cp.async.commit_group;"); }
template<int N> __device__ __forceinline__ void cpwait() {
    asm volatile("cp.async.wait_group %0;" :: "n"(N));
}

// -------- x transpose: g_xT[t][i][b] = input_signal[b][t][i] --------
__global__ void xT_kernel(const float* __restrict__ in) {
    __shared__ float s[128][33];
    int t = blockIdx.x >> 2, ig = blockIdx.x & 3;
    for (int idx = threadIdx.x; idx < 128 * 32; idx += 256) {
        int b = idx >> 5, ii = idx & 31;
        s[b][ii] = in[b * (Tn * NIN) + t * NIN + ig * 32 + ii];
    }
    __syncthreads();
    for (int idx = threadIdx.x; idx < 4096; idx += 256) {
        int ii = idx >> 7, b = idx & 127;
        g_xT[t * (NIN * Bn) + (ig * 32 + ii) * Bn + b] = s[b][ii];
    }
}

// -------- smem layout (float offsets) --------
#define SM_W    0                       // [1152][32] weights ([k][j])
#define SM_ACT  (SM_W + KTOT * 32)      // 3 x [128][32] act chunks (red aliases this)
#define SM_WO   (SM_ACT + 3 * 4096)     // [32][64] w_out slice
#define SM_HB   (SM_WO + 2048)          // h staged [b][j]  [32][36]
#define SM_TJ   (SM_HB + 32 * 36)       // tanh(h) [j][b]   [32][36]
#define SM_FLOATS (SM_TJ + 32 * 36)
#define SMEM_BYTES (SM_FLOATS * 4)

__global__ void __launch_bounds__(THREADS, 1)
rnn_main(const float* __restrict__ hidden,
         const float* __restrict__ w_in,
         const float* __restrict__ w_hh,
         const float* __restrict__ w_b,
         const float* __restrict__ w_out,
         const float* __restrict__ alpha,
         const float* __restrict__ noise,
         const int* __restrict__ ptp,
         float* __restrict__ out)
{
    extern __shared__ float sm[];
    float* w_s   = sm + SM_W;
    float* act_s = sm + SM_ACT;
    float* red   = act_s;                 // alias: [8][32][36] used after last chunk
    float* wo_s  = sm + SM_WO;
    float* hb    = sm + SM_HB;
    float* tj    = sm + SM_TJ;

    const int tid = threadIdx.x;
    const int cta = blockIdx.x;
    const int jg = cta & 31, bg = cta >> 5;
    const int jbase = jg * JSL, bbase = bg * 32;

    const int w   = tid >> 5;       // warp 0..15
    const int lid = tid & 31;
    const int kq  = w & 7;          // k-split group within chunk (rows kq, kq+8, ...)
    const int bh  = w >> 3;         // b-half 0/1
    const int jq  = lid & 3;        // j-quad -> 8 j at j0
    const int bq  = lid >> 2;       // 8 b-pairs
    const int j0  = jq * 8;
    const int b0  = bh * 16 + bq * 2;

    // ---- load weight slices into smem [k][32j] (once) ----
    {
        int jj = tid >> 4;          // 0..31
        int kk = tid & 15;          // 0..15
        const float* wr = w_hh + (size_t)(jbase + jj) * NHID;
        for (int k = kk; k < NHID; k += 16)
            w_s[k * 32 + jj] = wr[k];
        const float* wi = w_in + (size_t)(jbase + jj) * NIN;
        for (int i = kk; i < NIN; i += 16)
            w_s[(NHID + i) * 32 + jj] = wi[i];
    }
    for (int idx = tid; idx < JSL * 64; idx += THREADS) {
        int jj = idx >> 6, o = idx & 63;
        wo_s[jj * 64 + o] = w_out[o * NHID + jbase + jj];
    }

    // ---- per-thread h ownership: bloc = tid>>4, j = jp, jp+1 ----
    const int bloc = tid >> 4;
    const int jp = (tid & 15) * 2;
    const int bown = bbase + bloc;

    float2 al2 = *(const float2*)&alpha[jbase + jp];
    float2 bi2 = *(const float2*)&w_b[jbase + jp];
    float2 ns2 = make_float2(0.05f * sqrtf(al2.x), 0.05f * sqrtf(al2.y));
    const int pt = *ptp;

    float2 hv = *(const float2*)&hidden[(size_t)bown * NHID + jbase + jp];
    float h0 = hv.x, h1 = hv.y;

    // initial act buffer 0 = tanh(hidden), layout [k][b]
    g_act[0][(jbase + jp) * Bn + bown]     = tanhf(h0);
    g_act[0][(jbase + jp + 1) * Bn + bown] = tanhf(h1);

    // grid barrier (monotonic, replay-safe)
    unsigned bar_t = 0;
    if (tid == 0) bar_t = *((volatile unsigned*)&g_release);

#define GRIDBAR() do {                                                        \
        __threadfence();                                                      \
        __syncthreads();                                                      \
        if (tid == 0) {                                                       \
            bar_t += (unsigned)NCTA;                                          \
            unsigned a_ = atomicAdd(&g_arrive, 1u) + 1u;                      \
            if (a_ == bar_t) { atomicExch(&g_release, bar_t); }               \
            else { while ((int)(*((volatile unsigned*)&g_release) - bar_t) < 0) {} } \
        }                                                                     \
        __syncthreads();                                                      \
    } while (0)

    GRIDBAR();

    const uint32_t act_u = (uint32_t)__cvta_generic_to_shared(act_s);
    const int r0 = tid >> 3, cg = tid & 7;   // staging: each thread 1 float4 per 512

#define STAGE(SRC, BUFI) do {                                                 \
        const float* _s = (SRC);                                              \
        uint32_t _d = act_u + (uint32_t)((BUFI) * 4096 * 4);                  \
        cpasync16(_d + (uint32_t)((r0 * 32 + cg * 4) * 4),                    \
                  _s + r0 * Bn + bbase + cg * 4);                             \
        cpasync16(_d + (uint32_t)(((r0 + 64) * 32 + cg * 4) * 4),             \
                  _s + (r0 + 64) * Bn + bbase + cg * 4);                      \
        cpcommit();                                                           \
    } while (0)

    for (int t = 0; t < Tn; t++) {
        const float* asrc = g_act[t & 1];
        const float* xsrc = g_xT + t * (NIN * Bn);

        // prologue: stage chunks 0,1
        STAGE(asrc, 0);
        STAGE(asrc + 128 * Bn, 1);

        // overlap: deterministic reduce of previous step's out partials
        if (t > 0 && tid < 64) {
            int e = cta * 64 + tid;
            const float* src = g_outpart[(t - 1) & 1];
            float s = 0.f;
            #pragma unroll
            for (int r = 0; r < JGN; r++) s += __ldcg(src + r * (Bn * NOUT) + e);
            int b = e >> 6, o = e & 63;
            out[OUT_OUT + b * (Tn * NOUT) + (t - 1) * NOUT + o] = s;
        }

        ull acc[2][4];
        #pragma unroll
        for (int i = 0; i < 2; i++)
            #pragma unroll
            for (int j = 0; j < 4; j++) acc[i][j] = 0;

        #pragma unroll 1
        for (int c = 0; c < 9; c++) {
            if (c == 8) cpwait<0>(); else cpwait<1>();
            __syncthreads();
            if (c < 7) {
                const float* src = (c + 2 < 8) ? (asrc + (c + 2) * 128 * Bn) : xsrc;
                STAGE(src, (c + 2) % 3);
            }

            const float* abk = act_s + (c % 3) * 4096 + kq * 32 + b0;
            const float* wbk = w_s + (c * 128 + kq) * 32 + j0;
            #pragma unroll
            for (int i = 0; i < 16; i++) {
                float2 av = *(const float2*)(abk + i * 256);
                ulonglong2 w01 = *(const ulonglong2*)(wbk + i * 256);
                ulonglong2 w23 = *(const ulonglong2*)(wbk + i * 256 + 4);
                ull a0 = pack2(av.x), a1 = pack2(av.y);
                fma2(acc[0][0], a0, w01.x); fma2(acc[0][1], a0, w01.y);
                fma2(acc[0][2], a0, w23.x); fma2(acc[0][3], a0, w23.y);
                fma2(acc[1][0], a1, w01.x); fma2(acc[1][1], a1, w01.y);
                fma2(acc[1][2], a1, w23.x); fma2(acc[1][3], a1, w23.y);
            }
        }
        __syncthreads();   // all done computing chunk 8 before red dump (aliases act bufs)

        // ---- dump k-split partials: red[kq][b][36] ----
        {
            float* rd = red + ((size_t)(kq * 32 + b0)) * 36 + j0;
            *(ulonglong2*)(rd)      = make_ulonglong2(acc[0][0], acc[0][1]);
            *(ulonglong2*)(rd + 4)  = make_ulonglong2(acc[0][2], acc[0][3]);
            *(ulonglong2*)(rd + 36) = make_ulonglong2(acc[1][0], acc[1][1]);
            *(ulonglong2*)(rd + 40) = make_ulonglong2(acc[1][2], acc[1][3]);
        }
        __syncthreads();

        // ---- 8-way reduce + h update (thread owns bloc, jp..jp+1) ----
        {
            float s0 = bi2.x, s1 = bi2.y;
            #pragma unroll
            for (int g = 0; g < 8; g++) {
                float2 v = *(const float2*)(red + (g * 32 + bloc) * 36 + jp);
                s0 += v.x; s1 += v.y;
            }
            h0 = (1.f - al2.x) * h0 + al2.x * s0;
            h1 = (1.f - al2.y) * h1 + al2.y * s1;
            if (t == pt) {
                float2 n = *(const float2*)&noise[(size_t)bown * NHID + jbase + jp];
                h0 += n.x * ns2.x;
                h1 += n.y * ns2.y;
            }
        }

        // stage hb [b][j], tj [j][b]
        *(float2*)&hb[bloc * 36 + jp] = make_float2(h0, h1);
        tj[(jp)     * 36 + bloc] = tanhf(h0);
        tj[(jp + 1) * 36 + bloc] = tanhf(h1);
        __syncthreads();

        // coalesced global writes (256 threads)
        if (tid < 256) {
            int rw = tid >> 3, q = tid & 7;
            float4 v = *(const float4*)(hb + rw * 36 + q * 4);
            *(float4*)&out[OUT_HID + (size_t)(bbase + rw) * (Tn * NHID) + (size_t)t * NHID + jbase + q * 4] = v;
            if (t == Tn - 1)
                *(float4*)&out[OUT_HF + (size_t)(bbase + rw) * NHID + jbase + q * 4] = v;
            float4 a = *(const float4*)(tj + rw * 36 + q * 4);   // rw = local j row
            *(float4*)&g_act[(t + 1) & 1][(jbase + rw) * Bn + bbase + q * 4] = a;
        }

        // ---- out partial GEMM: [32b x 64o], K = 32 (this CTA's j slice) ----
        {
            const int br = tid >> 4;
            const int o0 = (tid & 15) * 4;
            float oa0 = 0.f, oa1 = 0.f, oa2 = 0.f, oa3 = 0.f;
            #pragma unroll
            for (int j = 0; j < JSL; j++) {
                float a = hb[br * 36 + j];
                float4 w4 = *(const float4*)(wo_s + j * 64 + o0);
                oa0 += a * w4.x; oa1 += a * w4.y; oa2 += a * w4.z; oa3 += a * w4.w;
            }
            float* op = g_outpart[t & 1] + jg * (Bn * NOUT);
            *(float4*)&op[(bbase + br) * 64 + o0] = make_float4(oa0, oa1, oa2, oa3);
        }

        GRIDBAR();
    }

    // final out reduce for t = 255
    if (tid < 64) {
        int e = cta * 64 + tid;
        const float* src = g_outpart[(Tn - 1) & 1];
        float s = 0.f;
        #pragma unroll
        for (int r = 0; r < JGN; r++) s += __ldcg(src + r * (Bn * NOUT) + e);
        int b = e >> 6, o = e & 63;
        out[OUT_OUT + b * (Tn * NOUT) + (Tn - 1) * NOUT + o] = s;
    }
#undef GRIDBAR
#undef STAGE
}

// -------- launcher --------
extern "C" void kernel_launch(void* const* d_in, const int* in_sizes, int n_in,
                              void* d_out, int out_size)
{
    const float* input_signal = (const float*)d_in[0];
    const float* hidden       = (const float*)d_in[1];
    const float* w_in_w       = (const float*)d_in[2];
    const float* w_hh_w       = (const float*)d_in[3];
    const float* w_hh_b       = (const float*)d_in[4];
    const float* w_out_w      = (const float*)d_in[5];
    const float* alpha        = (const float*)d_in[6];
    const float* noise_raw    = (const float*)d_in[7];
    const int*   pt           = (const int*)d_in[8];
    float* out = (float*)d_out;

    cudaFuncSetAttribute(rnn_main, cudaFuncAttributeMaxDynamicSharedMemorySize, SMEM_BYTES);

    xT_kernel<<<1024, 256>>>(input_signal);
    rnn_main<<<NCTA, THREADS, SMEM_BYTES>>>(hidden, w_in_w, w_hh_w, w_hh_b,
                                            w_out_w, alpha, noise_raw, pt, out);
}

// round 6
// speedup vs baseline: 2.2117x; 1.2745x over previous
#include <cuda_runtime.h>
#include <cuda_bf16.h>
#include <cstdint>

#define Bn 128
#define Tn 256
#define NHID 1024
#define NIN 128
#define NOUT 64
#define KTOT 1152
#define NCTA 128
#define THREADS 512
#define JGN 32          // j-groups
#define JSL 32          // j per CTA

// output layout: hidden_list [128][256][1024] ++ output_list [128][256][64] ++ h_final [128][1024]
#define OUT_HID 0
#define OUT_OUT 33554432
#define OUT_HF  35651584

// -------- device scratch --------
__device__ float g_act[2][NHID * Bn];              // tanh(h) [k][b], double buffered
__device__ float g_xT[Tn * NIN * Bn];              // x transposed [t][i][b]
__device__ float g_outpart[2][JGN * Bn * NOUT];    // out partials [jg][b*64+o]
__device__ unsigned g_arrive;
__device__ unsigned g_release;

typedef unsigned long long ull;

__device__ __forceinline__ ull pack2(float x) {
    ull r; asm("mov.b64 %0, {%1, %1};" : "=l"(r) : "f"(x)); return r;
}
__device__ __forceinline__ void fma2(ull& c, ull a, ull b) {
    asm("fma.rn.f32x2 %0, %1, %2, %0;" : "+l"(c) : "l"(a), "l"(b));
}
__device__ __forceinline__ float2 unpack2(ull v) {
    float2 f; asm("mov.b64 {%0, %1}, %2;" : "=f"(f.x), "=f"(f.y) : "l"(v)); return f;
}
__device__ __forceinline__ void cpasync16(uint32_t dst, const float* src) {
    asm volatile("cp.async.cg.shared.global [%0], [%1], 16;" :: "r"(dst), "l"(src));
}
__device__ __forceinline__ void cpcommit() { asm volatile("cp.async.commit_group;"); }
template<int N> __device__ __forceinline__ void cpwait() {
    asm volatile("cp.async.wait_group %0;" :: "n"(N));
}

// fast exact-formula tanh: 1 - 2/(exp(2x)+1) via MUFU (rel err ~1e-6..1e-5)
__device__ __forceinline__ float fast_tanh(float x) {
    float e;
    asm("ex2.approx.f32 %0, %1;" : "=f"(e) : "f"(x * 2.8853900817779268f));
    float r;
    asm("rcp.approx.f32 %0, %1;" : "=f"(r) : "f"(e + 1.0f));
    return __fmaf_rn(-2.0f, r, 1.0f);
}

// -------- x transpose: g_xT[t][i][b] = input_signal[b][t][i] --------
__global__ void xT_kernel(const float* __restrict__ in) {
    __shared__ float s[128][33];
    int t = blockIdx.x >> 2, ig = blockIdx.x & 3;
    for (int idx = threadIdx.x; idx < 128 * 32; idx += 256) {
        int b = idx >> 5, ii = idx & 31;
        s[b][ii] = in[b * (Tn * NIN) + t * NIN + ig * 32 + ii];
    }
    __syncthreads();
    for (int idx = threadIdx.x; idx < 4096; idx += 256) {
        int ii = idx >> 7, b = idx & 127;
        g_xT[t * (NIN * Bn) + (ig * 32 + ii) * Bn + b] = s[b][ii];
    }
}

// -------- smem layout (float offsets) --------
#define SM_W    0                       // [1152][32] weights ([k][j])
#define SM_ACT  (SM_W + KTOT * 32)      // 3 x [128][32] act chunks (red aliases this)
#define SM_WO   (SM_ACT + 3 * 4096)     // [32][64] w_out slice
#define SM_HB   (SM_WO + 2048)          // h staged [b][j]  [32][36]
#define SM_TJ   (SM_HB + 32 * 36)       // tanh(h) [j][b]   [32][36]
#define SM_FLOATS (SM_TJ + 32 * 36)
#define SMEM_BYTES (SM_FLOATS * 4)

__global__ void __launch_bounds__(THREADS, 1)
rnn_main(const float* __restrict__ hidden,
         const float* __restrict__ w_in,
         const float* __restrict__ w_hh,
         const float* __restrict__ w_b,
         const float* __restrict__ w_out,
         const float* __restrict__ alpha,
         const float* __restrict__ noise,
         const int* __restrict__ ptp,
         float* __restrict__ out)
{
    extern __shared__ float sm[];
    float* w_s   = sm + SM_W;
    float* act_s = sm + SM_ACT;
    float* red   = act_s;                 // alias: [8][32][36] floats = 9216 <= 12288
    float* wo_s  = sm + SM_WO;
    float* hb    = sm + SM_HB;
    float* tj    = sm + SM_TJ;

    const int tid = threadIdx.x;
    const int cta = blockIdx.x;
    const int jg = cta & 31, bg = cta >> 5;
    const int jbase = jg * JSL, bbase = bg * 32;

    const int w   = tid >> 5;       // warp 0..15 : k-row owner (16-way k split)
    const int lid = tid & 31;
    const int bq  = lid & 7;        // b-quad -> 4 b at b0
    const int jq  = lid >> 3;       // j-oct  -> 8 j at j0
    const int b0  = bq * 4;
    const int j0  = jq * 8;

    // ---- load weight slices into smem [k][32j] (once) ----
    {
        int jj = tid >> 4;          // 0..31
        int kk = tid & 15;          // 0..15
        const float* wr = w_hh + (size_t)(jbase + jj) * NHID;
        for (int k = kk; k < NHID; k += 16)
            w_s[k * 32 + jj] = wr[k];
        const float* wi = w_in + (size_t)(jbase + jj) * NIN;
        for (int i = kk; i < NIN; i += 16)
            w_s[(NHID + i) * 32 + jj] = wi[i];
    }
    for (int idx = tid; idx < JSL * 64; idx += THREADS) {
        int jj = idx >> 6, o = idx & 63;
        wo_s[jj * 64 + o] = w_out[o * NHID + jbase + jj];
    }

    // ---- per-thread h ownership: bloc = tid>>4, j = jp, jp+1 ----
    const int bloc = tid >> 4;
    const int jp = (tid & 15) * 2;
    const int bown = bbase + bloc;

    float2 al2 = *(const float2*)&alpha[jbase + jp];
    float2 bi2 = *(const float2*)&w_b[jbase + jp];
    float2 ns2 = make_float2(0.05f * sqrtf(al2.x), 0.05f * sqrtf(al2.y));
    const int pt = *ptp;

    float2 hv = *(const float2*)&hidden[(size_t)bown * NHID + jbase + jp];
    float h0 = hv.x, h1 = hv.y;

    // initial act buffer 0 = tanh(hidden), layout [k][b]
    g_act[0][(jbase + jp) * Bn + bown]     = fast_tanh(h0);
    g_act[0][(jbase + jp + 1) * Bn + bown] = fast_tanh(h1);

    // grid barrier (monotonic, replay-safe)
    unsigned bar_t = 0;
    if (tid == 0) bar_t = *((volatile unsigned*)&g_release);

#define GRIDBAR() do {                                                        \
        __threadfence();                                                      \
        __syncthreads();                                                      \
        if (tid == 0) {                                                       \
            bar_t += (unsigned)NCTA;                                          \
            unsigned a_ = atomicAdd(&g_arrive, 1u) + 1u;                      \
            if (a_ == bar_t) { atomicExch(&g_release, bar_t); }               \
            else { while ((int)(*((volatile unsigned*)&g_release) - bar_t) < 0) {} } \
        }                                                                     \
        __syncthreads();                                                      \
    } while (0)

    GRIDBAR();

    const uint32_t act_u = (uint32_t)__cvta_generic_to_shared(act_s);
    const int r0 = tid >> 3, cg = tid & 7;   // staging map

#define STAGE(SRC, BUFI) do {                                                 \
        const float* _s = (SRC);                                              \
        uint32_t _d = act_u + (uint32_t)((BUFI) * 4096 * 4);                  \
        cpasync16(_d + (uint32_t)((r0 * 32 + cg * 4) * 4),                    \
                  _s + r0 * Bn + bbase + cg * 4);                             \
        cpasync16(_d + (uint32_t)(((r0 + 64) * 32 + cg * 4) * 4),             \
                  _s + (r0 + 64) * Bn + bbase + cg * 4);                      \
        cpcommit();                                                           \
    } while (0)

    for (int t = 0; t < Tn; t++) {
        const float* asrc = g_act[t & 1];
        const float* xsrc = g_xT + t * (NIN * Bn);

        // prologue: stage chunks 0,1
        STAGE(asrc, 0);
        STAGE(asrc + 128 * Bn, 1);

        // overlap: deterministic reduce of previous step's out partials
        if (t > 0 && tid < 64) {
            int e = cta * 64 + tid;
            const float* src = g_outpart[(t - 1) & 1];
            float s = 0.f;
            #pragma unroll
            for (int r = 0; r < JGN; r++) s += __ldcg(src + r * (Bn * NOUT) + e);
            int b = e >> 6, o = e & 63;
            out[OUT_OUT + b * (Tn * NOUT) + (t - 1) * NOUT + o] = s;
        }

        ull acc[4][4];
        #pragma unroll
        for (int i = 0; i < 4; i++)
            #pragma unroll
            for (int j = 0; j < 4; j++) acc[i][j] = 0;

        #pragma unroll 1
        for (int c = 0; c < 9; c++) {
            if (c == 8) cpwait<0>(); else cpwait<1>();
            __syncthreads();
            if (c < 7) {
                const float* src = (c + 2 < 8) ? (asrc + (c + 2) * 128 * Bn) : xsrc;
                STAGE(src, (c + 2) % 3);
            }

            // warp w computes rows w*8 .. w*8+7 of this chunk
            const float* abk = act_s + (c % 3) * 4096 + (w * 8) * 32 + b0;
            const float* wbk = w_s + (c * 128 + w * 8) * 32 + j0;
            #pragma unroll
            for (int i = 0; i < 8; i++) {
                float4 av = *(const float4*)(abk + i * 32);
                ulonglong2 w01 = *(const ulonglong2*)(wbk + i * 32);
                ulonglong2 w23 = *(const ulonglong2*)(wbk + i * 32 + 4);
                ull a0 = pack2(av.x), a1 = pack2(av.y);
                ull a2 = pack2(av.z), a3 = pack2(av.w);
                fma2(acc[0][0], a0, w01.x); fma2(acc[0][1], a0, w01.y);
                fma2(acc[0][2], a0, w23.x); fma2(acc[0][3], a0, w23.y);
                fma2(acc[1][0], a1, w01.x); fma2(acc[1][1], a1, w01.y);
                fma2(acc[1][2], a1, w23.x); fma2(acc[1][3], a1, w23.y);
                fma2(acc[2][0], a2, w01.x); fma2(acc[2][1], a2, w01.y);
                fma2(acc[2][2], a2, w23.x); fma2(acc[2][3], a2, w23.y);
                fma2(acc[3][0], a3, w01.x); fma2(acc[3][1], a3, w01.y);
                fma2(acc[3][2], a3, w23.x); fma2(acc[3][3], a3, w23.y);
            }
        }
        __syncthreads();   // protect act buffers (red alias) until chunk 8 done

        // ---- 16-way k-split reduce, deterministic ----
        // phase 0: warps 8..15 dump partials to red[w-8]
        if (w >= 8) {
            float* rd = red + (w - 8) * (32 * 36);
            #pragma unroll
            for (int bb = 0; bb < 4; bb++) {
                float2 v0 = unpack2(acc[bb][0]);
                float2 v1 = unpack2(acc[bb][1]);
                float2 v2 = unpack2(acc[bb][2]);
                float2 v3 = unpack2(acc[bb][3]);
                *(float4*)(rd + (b0 + bb) * 36 + j0)     = make_float4(v0.x, v0.y, v1.x, v1.y);
                *(float4*)(rd + (b0 + bb) * 36 + j0 + 4) = make_float4(v2.x, v2.y, v3.x, v3.y);
            }
        }
        __syncthreads();
        // phase 1: warps 0..7 add partner partials, write back
        if (w < 8) {
            float* rd = red + w * (32 * 36);
            #pragma unroll
            for (int bb = 0; bb < 4; bb++) {
                float4 p0 = *(const float4*)(rd + (b0 + bb) * 36 + j0);
                float4 p1 = *(const float4*)(rd + (b0 + bb) * 36 + j0 + 4);
                float2 v0 = unpack2(acc[bb][0]);
                float2 v1 = unpack2(acc[bb][1]);
                float2 v2 = unpack2(acc[bb][2]);
                float2 v3 = unpack2(acc[bb][3]);
                *(float4*)(rd + (b0 + bb) * 36 + j0) =
                    make_float4(v0.x + p0.x, v0.y + p0.y, v1.x + p0.z, v1.y + p0.w);
                *(float4*)(rd + (b0 + bb) * 36 + j0 + 4) =
                    make_float4(v2.x + p1.x, v2.y + p1.y, v3.x + p1.z, v3.y + p1.w);
            }
        }
        __syncthreads();

        // ---- phase 2: 8-way reduce + h update (thread owns bloc, jp..jp+1) ----
        {
            float s0 = bi2.x, s1 = bi2.y;
            #pragma unroll
            for (int g = 0; g < 8; g++) {
                float2 v = *(const float2*)(red + g * (32 * 36) + bloc * 36 + jp);
                s0 += v.x; s1 += v.y;
            }
            h0 = (1.f - al2.x) * h0 + al2.x * s0;
            h1 = (1.f - al2.y) * h1 + al2.y * s1;
            if (t == pt) {
                float2 n = *(const float2*)&noise[(size_t)bown * NHID + jbase + jp];
                h0 += n.x * ns2.x;
                h1 += n.y * ns2.y;
            }
        }

        // stage hb [b][j], tj [j][b]
        *(float2*)&hb[bloc * 36 + jp] = make_float2(h0, h1);
        tj[(jp)     * 36 + bloc] = fast_tanh(h0);
        tj[(jp + 1) * 36 + bloc] = fast_tanh(h1);
        __syncthreads();

        // coalesced global writes (256 threads)
        if (tid < 256) {
            int rw = tid >> 3, q = tid & 7;
            float4 v = *(const float4*)(hb + rw * 36 + q * 4);
            *(float4*)&out[OUT_HID + (size_t)(bbase + rw) * (Tn * NHID) + (size_t)t * NHID + jbase + q * 4] = v;
            if (t == Tn - 1)
                *(float4*)&out[OUT_HF + (size_t)(bbase + rw) * NHID + jbase + q * 4] = v;
            float4 a = *(const float4*)(tj + rw * 36 + q * 4);   // rw = local j row
            *(float4*)&g_act[(t + 1) & 1][(jbase + rw) * Bn + bbase + q * 4] = a;
        }

        // ---- out partial GEMM: [32b x 64o], K = 32 (this CTA's j slice) ----
        {
            const int br = tid >> 4;
            const int o0 = (tid & 15) * 4;
            float oa0 = 0.f, oa1 = 0.f, oa2 = 0.f, oa3 = 0.f;
            #pragma unroll
            for (int j = 0; j < JSL; j++) {
                float a = hb[br * 36 + j];
                float4 w4 = *(const float4*)(wo_s + j * 64 + o0);
                oa0 += a * w4.x; oa1 += a * w4.y; oa2 += a * w4.z; oa3 += a * w4.w;
            }
            float* op = g_outpart[t & 1] + jg * (Bn * NOUT);
            *(float4*)&op[(bbase + br) * 64 + o0] = make_float4(oa0, oa1, oa2, oa3);
        }

        GRIDBAR();
    }

    // final out reduce for t = 255
    if (tid < 64) {
        int e = cta * 64 + tid;
        const float* src = g_outpart[(Tn - 1) & 1];
        float s = 0.f;
        #pragma unroll
        for (int r = 0; r < JGN; r++) s += __ldcg(src + r * (Bn * NOUT) + e);
        int b = e >> 6, o = e & 63;
        out[OUT_OUT + b * (Tn * NOUT) + (Tn - 1) * NOUT + o] = s;
    }
#undef GRIDBAR
#undef STAGE
}

// -------- launcher --------
extern "C" void kernel_launch(void* const* d_in, const int* in_sizes, int n_in,
                              void* d_out, int out_size)
{
    const float* input_signal = (const float*)d_in[0];
    const float* hidden       = (const float*)d_in[1];
    const float* w_in_w       = (const float*)d_in[2];
    const float* w_hh_w       = (const float*)d_in[3];
    const float* w_hh_b       = (const float*)d_in[4];
    const float* w_out_w      = (const float*)d_in[5];
    const float* alpha        = (const float*)d_in[6];
    const float* noise_raw    = (const float*)d_in[7];
    const int*   pt           = (const int*)d_in[8];
    float* out = (float*)d_out;

    cudaFuncSetAttribute(rnn_main, cudaFuncAttributeMaxDynamicSharedMemorySize, SMEM_BYTES);

    xT_kernel<<<1024, 256>>>(input_signal);
    rnn_main<<<NCTA, THREADS, SMEM_BYTES>>>(hidden, w_in_w, w_hh_w, w_hh_b,
                                            w_out_w, alpha, noise_raw, pt, out);
}

// round 7
// speedup vs baseline: 2.4332x; 1.1002x over previous
#include <cuda_runtime.h>
#include <cuda_bf16.h>
#include <cstdint>

#define Bn 128
#define Tn 256
#define NHID 1024
#define NIN 128
#define NOUT 64
#define KTOT 1152
#define NCTA 128
#define THREADS 512
#define JGN 32          // j-groups
#define JSL 32          // j per CTA

// output layout: hidden_list [128][256][1024] ++ output_list [128][256][64] ++ h_final [128][1024]
#define OUT_HID 0
#define OUT_OUT 33554432
#define OUT_HF  35651584

// -------- device scratch --------
__device__ float g_act[2][NHID * Bn];              // tanh(h) [k][b], double buffered
__device__ float g_xT[Tn * NIN * Bn];              // x transposed [t][i][b]
__device__ float g_outpart[2][JGN * Bn * NOUT];    // out partials [jg][b*64+o]
__device__ unsigned g_arrive4[128];                // per-bg barrier counters (stride 32)
__device__ unsigned g_release4[128];

typedef unsigned long long ull;

__device__ __forceinline__ ull pack2(float x) {
    ull r; asm("mov.b64 %0, {%1, %1};" : "=l"(r) : "f"(x)); return r;
}
__device__ __forceinline__ void fma2(ull& c, ull a, ull b) {
    asm("fma.rn.f32x2 %0, %1, %2, %0;" : "+l"(c) : "l"(a), "l"(b));
}
__device__ __forceinline__ float2 unpack2(ull v) {
    float2 f; asm("mov.b64 {%0, %1}, %2;" : "=f"(f.x), "=f"(f.y) : "l"(v)); return f;
}
__device__ __forceinline__ void cpasync16(uint32_t dst, const float* src) {
    asm volatile("cp.async.cg.shared.global [%0], [%1], 16;" :: "r"(dst), "l"(src));
}
__device__ __forceinline__ void cpcommit() { asm volatile("cp.async.commit_group;"); }
template<int N> __device__ __forceinline__ void cpwait() {
    asm volatile("cp.async.wait_group %0;" :: "n"(N));
}

// fast exact-formula tanh: 1 - 2/(exp(2x)+1) via MUFU (rel err ~1e-6..1e-5)
__device__ __forceinline__ float fast_tanh(float x) {
    float e;
    asm("ex2.approx.f32 %0, %1;" : "=f"(e) : "f"(x * 2.8853900817779268f));
    float r;
    asm("rcp.approx.f32 %0, %1;" : "=f"(r) : "f"(e + 1.0f));
    return __fmaf_rn(-2.0f, r, 1.0f);
}

// -------- x transpose: g_xT[t][i][b] = input_signal[b][t][i] --------
__global__ void xT_kernel(const float* __restrict__ in) {
    __shared__ float s[128][33];
    int t = blockIdx.x >> 2, ig = blockIdx.x & 3;
    for (int idx = threadIdx.x; idx < 128 * 32; idx += 256) {
        int b = idx >> 5, ii = idx & 31;
        s[b][ii] = in[b * (Tn * NIN) + t * NIN + ig * 32 + ii];
    }
    __syncthreads();
    for (int idx = threadIdx.x; idx < 4096; idx += 256) {
        int ii = idx >> 7, b = idx & 127;
        g_xT[t * (NIN * Bn) + (ig * 32 + ii) * Bn + b] = s[b][ii];
    }
}

// -------- smem layout (float offsets) --------
#define SM_W    0                       // [1152][32] weights ([k][j])
#define SM_ACT  (SM_W + KTOT * 32)      // act_w[16][3][256] private rings (red aliases)
#define SM_WO   (SM_ACT + 16 * 768)     // [32][64] w_out slice
#define SM_HB   (SM_WO + 2048)          // h staged [b][j]  [32][36]
#define SM_TJ   (SM_HB + 32 * 36)       // tanh(h) [j][b]   [32][36]
#define SM_FLOATS (SM_TJ + 32 * 36)
#define SMEM_BYTES (SM_FLOATS * 4)

__global__ void __launch_bounds__(THREADS, 1)
rnn_main(const float* __restrict__ hidden,
         const float* __restrict__ w_in,
         const float* __restrict__ w_hh,
         const float* __restrict__ w_b,
         const float* __restrict__ w_out,
         const float* __restrict__ alpha,
         const float* __restrict__ noise,
         const int* __restrict__ ptp,
         float* __restrict__ out)
{
    extern __shared__ float sm[];
    float* w_s   = sm + SM_W;
    float* act_s = sm + SM_ACT;
    float* red   = act_s;                 // alias: [8][32][36] = 9216 <= 12288 floats
    float* wo_s  = sm + SM_WO;
    float* hb    = sm + SM_HB;
    float* tj    = sm + SM_TJ;

    const int tid = threadIdx.x;
    const int cta = blockIdx.x;
    const int jg = cta & 31, bg = cta >> 5;
    const int jbase = jg * JSL, bbase = bg * 32;

    const int w   = tid >> 5;       // warp 0..15 : owns rows w*8..w*8+7 per chunk
    const int lid = tid & 31;
    const int bq  = lid & 7;        // -> 4 b at b0
    const int jq  = lid >> 3;       // -> 8 j at j0
    const int b0  = bq * 4;
    const int j0  = jq * 8;

    // ---- load weight slices into smem [k][32j] (once) ----
    {
        int jj = tid >> 4;          // 0..31
        int kk = tid & 15;          // 0..15
        const float* wr = w_hh + (size_t)(jbase + jj) * NHID;
        for (int k = kk; k < NHID; k += 16)
            w_s[k * 32 + jj] = wr[k];
        const float* wi = w_in + (size_t)(jbase + jj) * NIN;
        for (int i = kk; i < NIN; i += 16)
            w_s[(NHID + i) * 32 + jj] = wi[i];
    }
    for (int idx = tid; idx < JSL * 64; idx += THREADS) {
        int jj = idx >> 6, o = idx & 63;
        wo_s[jj * 64 + o] = w_out[o * NHID + jbase + jj];
    }

    // ---- per-thread h ownership: bloc = tid>>4, j = jp, jp+1 ----
    const int bloc = tid >> 4;
    const int jp = (tid & 15) * 2;
    const int bown = bbase + bloc;

    float2 al2 = *(const float2*)&alpha[jbase + jp];
    float2 bi2 = *(const float2*)&w_b[jbase + jp];
    float2 ns2 = make_float2(0.05f * sqrtf(al2.x), 0.05f * sqrtf(al2.y));
    const int pt = *ptp;

    float2 hv = *(const float2*)&hidden[(size_t)bown * NHID + jbase + jp];
    float h0 = hv.x, h1 = hv.y;

    // initial act buffer 0 = tanh(hidden), layout [k][b]
    g_act[0][(jbase + jp) * Bn + bown]     = fast_tanh(h0);
    g_act[0][(jbase + jp + 1) * Bn + bown] = fast_tanh(h1);

    // per-bg grid barrier (32 CTAs; dependency graph is closed within bg group)
    unsigned bar_t = 0;
    if (tid == 0) bar_t = *((volatile unsigned*)&g_release4[bg * 32]);

#define GRIDBAR() do {                                                        \
        __threadfence();                                                      \
        __syncthreads();                                                      \
        if (tid == 0) {                                                       \
            bar_t += 32u;                                                     \
            unsigned a_ = atomicAdd(&g_arrive4[bg * 32], 1u) + 1u;            \
            if (a_ == bar_t) { atomicExch(&g_release4[bg * 32], bar_t); }     \
            else { while ((int)(*((volatile unsigned*)&g_release4[bg * 32]) - bar_t) < 0) {} } \
        }                                                                     \
        __syncthreads();                                                      \
    } while (0)

    GRIDBAR();

    // warp-private act ring: act_w[w][3][256]
    const uint32_t actw_u = (uint32_t)__cvta_generic_to_shared(act_s) + (uint32_t)(w * 768 * 4);
    const float* actw = act_s + w * 768;
    const int srow = lid >> 2;              // staging row 0..7
    const int scol = (lid & 3) * 8;         // staging col 0..24 (8 floats = 2x16B)

    // stage warp-own rows of one chunk into ring slot BUFI
#define WSTAGE(BASE, BUFI) do {                                               \
        const float* _s = (BASE) + (w * 8 + srow) * Bn + bbase + scol;        \
        uint32_t _d = actw_u + (uint32_t)(((BUFI) * 256 + srow * 32 + scol) * 4); \
        cpasync16(_d,      _s);                                               \
        cpasync16(_d + 16, _s + 4);                                           \
        cpcommit();                                                           \
    } while (0)

    for (int t = 0; t < Tn; t++) {
        const float* asrc = g_act[t & 1];
        const float* xsrc = g_xT + t * (NIN * Bn);

        // prologue: stage chunks 0,1 (warp-private)
        WSTAGE(asrc, 0);
        WSTAGE(asrc + 128 * Bn, 1);

        // overlap: deterministic reduce of previous step's out partials
        if (t > 0 && tid < 64) {
            int e = cta * 64 + tid;
            const float* src = g_outpart[(t - 1) & 1];
            float s = 0.f;
            #pragma unroll
            for (int r = 0; r < JGN; r++) s += __ldcg(src + r * (Bn * NOUT) + e);
            int b = e >> 6, o = e & 63;
            out[OUT_OUT + b * (Tn * NOUT) + (t - 1) * NOUT + o] = s;
        }

        ull acc[4][4];
        #pragma unroll
        for (int i = 0; i < 4; i++)
            #pragma unroll
            for (int j = 0; j < 4; j++) acc[i][j] = 0;

        // ---- 9-chunk GEMM, NO block syncs: warps free-run on private rings ----
        #pragma unroll 1
        for (int c = 0; c < 9; c++) {
            if (c < 7) {
                const float* base = (c + 2 < 8) ? (asrc + (c + 2) * 128 * Bn) : xsrc;
                WSTAGE(base, (c + 2) % 3);
                cpwait<2>();
            } else if (c == 7) {
                cpwait<1>();
            } else {
                cpwait<0>();
            }
            __syncwarp();

            const float* abk = actw + (c % 3) * 256 + b0;
            const float* wbk = w_s + (c * 128 + w * 8) * 32 + j0;
            #pragma unroll
            for (int i = 0; i < 8; i++) {
                float4 av = *(const float4*)(abk + i * 32);
                ulonglong2 w01 = *(const ulonglong2*)(wbk + i * 32);
                ulonglong2 w23 = *(const ulonglong2*)(wbk + i * 32 + 4);
                ull a0 = pack2(av.x), a1 = pack2(av.y);
                ull a2 = pack2(av.z), a3 = pack2(av.w);
                fma2(acc[0][0], a0, w01.x); fma2(acc[0][1], a0, w01.y);
                fma2(acc[0][2], a0, w23.x); fma2(acc[0][3], a0, w23.y);
                fma2(acc[1][0], a1, w01.x); fma2(acc[1][1], a1, w01.y);
                fma2(acc[1][2], a1, w23.x); fma2(acc[1][3], a1, w23.y);
                fma2(acc[2][0], a2, w01.x); fma2(acc[2][1], a2, w01.y);
                fma2(acc[2][2], a2, w23.x); fma2(acc[2][3], a2, w23.y);
                fma2(acc[3][0], a3, w01.x); fma2(acc[3][1], a3, w01.y);
                fma2(acc[3][2], a3, w23.x); fma2(acc[3][3], a3, w23.y);
            }
        }
        __syncthreads();   // all warps done with act rings (red aliases them)

        // ---- 16-way k-split reduce, deterministic ----
        if (w >= 8) {
            float* rd = red + (w - 8) * (32 * 36);
            #pragma unroll
            for (int bb = 0; bb < 4; bb++) {
                float2 v0 = unpack2(acc[bb][0]);
                float2 v1 = unpack2(acc[bb][1]);
                float2 v2 = unpack2(acc[bb][2]);
                float2 v3 = unpack2(acc[bb][3]);
                *(float4*)(rd + (b0 + bb) * 36 + j0)     = make_float4(v0.x, v0.y, v1.x, v1.y);
                *(float4*)(rd + (b0 + bb) * 36 + j0 + 4) = make_float4(v2.x, v2.y, v3.x, v3.y);
            }
        }
        __syncthreads();
        if (w < 8) {
            float* rd = red + w * (32 * 36);
            #pragma unroll
            for (int bb = 0; bb < 4; bb++) {
                float4 p0 = *(const float4*)(rd + (b0 + bb) * 36 + j0);
                float4 p1 = *(const float4*)(rd + (b0 + bb) * 36 + j0 + 4);
                float2 v0 = unpack2(acc[bb][0]);
                float2 v1 = unpack2(acc[bb][1]);
                float2 v2 = unpack2(acc[bb][2]);
                float2 v3 = unpack2(acc[bb][3]);
                *(float4*)(rd + (b0 + bb) * 36 + j0) =
                    make_float4(v0.x + p0.x, v0.y + p0.y, v1.x + p0.z, v1.y + p0.w);
                *(float4*)(rd + (b0 + bb) * 36 + j0 + 4) =
                    make_float4(v2.x + p1.x, v2.y + p1.y, v3.x + p1.z, v3.y + p1.w);
            }
        }
        __syncthreads();

        // ---- 8-way reduce + h update (thread owns bloc, jp..jp+1) ----
        {
            float s0 = bi2.x, s1 = bi2.y;
            #pragma unroll
            for (int g = 0; g < 8; g++) {
                float2 v = *(const float2*)(red + g * (32 * 36) + bloc * 36 + jp);
                s0 += v.x; s1 += v.y;
            }
            h0 = (1.f - al2.x) * h0 + al2.x * s0;
            h1 = (1.f - al2.y) * h1 + al2.y * s1;
            if (t == pt) {
                float2 n = *(const float2*)&noise[(size_t)bown * NHID + jbase + jp];
                h0 += n.x * ns2.x;
                h1 += n.y * ns2.y;
            }
        }

        // stage hb [b][j], tj [j][b]
        *(float2*)&hb[bloc * 36 + jp] = make_float2(h0, h1);
        tj[(jp)     * 36 + bloc] = fast_tanh(h0);
        tj[(jp + 1) * 36 + bloc] = fast_tanh(h1);
        __syncthreads();

        // coalesced global writes (256 threads)
        if (tid < 256) {
            int rw = tid >> 3, q = tid & 7;
            float4 v = *(const float4*)(hb + rw * 36 + q * 4);
            *(float4*)&out[OUT_HID + (size_t)(bbase + rw) * (Tn * NHID) + (size_t)t * NHID + jbase + q * 4] = v;
            if (t == Tn - 1)
                *(float4*)&out[OUT_HF + (size_t)(bbase + rw) * NHID + jbase + q * 4] = v;
            float4 a = *(const float4*)(tj + rw * 36 + q * 4);   // rw = local j row
            *(float4*)&g_act[(t + 1) & 1][(jbase + rw) * Bn + bbase + q * 4] = a;
        }

        // ---- out partial GEMM: [32b x 64o], K = 32 (this CTA's j slice) ----
        {
            const int br = tid >> 4;
            const int o0 = (tid & 15) * 4;
            float oa0 = 0.f, oa1 = 0.f, oa2 = 0.f, oa3 = 0.f;
            #pragma unroll
            for (int j = 0; j < JSL; j++) {
                float a = hb[br * 36 + j];
                float4 w4 = *(const float4*)(wo_s + j * 64 + o0);
                oa0 += a * w4.x; oa1 += a * w4.y; oa2 += a * w4.z; oa3 += a * w4.w;
            }
            float* op = g_outpart[t & 1] + jg * (Bn * NOUT);
            *(float4*)&op[(bbase + br) * 64 + o0] = make_float4(oa0, oa1, oa2, oa3);
        }

        GRIDBAR();
    }

    // final out reduce for t = 255
    if (tid < 64) {
        int e = cta * 64 + tid;
        const float* src = g_outpart[(Tn - 1) & 1];
        float s = 0.f;
        #pragma unroll
        for (int r = 0; r < JGN; r++) s += __ldcg(src + r * (Bn * NOUT) + e);
        int b = e >> 6, o = e & 63;
        out[OUT_OUT + b * (Tn * NOUT) + (Tn - 1) * NOUT + o] = s;
    }
#undef GRIDBAR
#undef WSTAGE
}

// -------- launcher --------
extern "C" void kernel_launch(void* const* d_in, const int* in_sizes, int n_in,
                              void* d_out, int out_size)
{
    const float* input_signal = (const float*)d_in[0];
    const float* hidden       = (const float*)d_in[1];
    const float* w_in_w       = (const float*)d_in[2];
    const float* w_hh_w       = (const float*)d_in[3];
    const float* w_hh_b       = (const float*)d_in[4];
    const float* w_out_w      = (const float*)d_in[5];
    const float* alpha        = (const float*)d_in[6];
    const float* noise_raw    = (const float*)d_in[7];
    const int*   pt           = (const int*)d_in[8];
    float* out = (float*)d_out;

    cudaFuncSetAttribute(rnn_main, cudaFuncAttributeMaxDynamicSharedMemorySize, SMEM_BYTES);

    xT_kernel<<<1024, 256>>>(input_signal);
    rnn_main<<<NCTA, THREADS, SMEM_BYTES>>>(hidden, w_in_w, w_hh_w, w_hh_b,
                                            w_out_w, alpha, noise_raw, pt, out);
}